// round 10
// baseline (speedup 1.0000x reference)
#include <cuda_runtime.h>
#include <cstdint>
#include <mma.h>

using namespace nvcuda;

#define B_      8
#define C_      256
#define H_      128
#define W_      128
#define HW_     (H_ * W_)
#define GROUPS_ 32
#define CPG_    8
#define EPS_    1e-5f
#define AST     68

typedef unsigned long long u64;

// ---------------------------------------------------------------------------
// Scratch
// ---------------------------------------------------------------------------
__device__ float  g_Yq[(size_t)B_ * C_ * HW_];
__device__ float  g_Yk[(size_t)B_ * C_ * HW_];
__device__ float  g_Whi[2][C_ * C_];           // tf32(v)
__device__ float  g_Wlo[2][C_ * C_];           // tf32(v - tf32(v))
__device__ float  g_psum[2][B_][GROUPS_][2];
__device__ float2 g_stats[2][B_][GROUPS_];

// ---------------------------------------------------------------------------
// fp32x2 helpers (attn kernel)
// ---------------------------------------------------------------------------
#define FMA2(acc, a, b) asm("fma.rn.f32x2 %0, %1, %2, %0;" : "+l"(acc) : "l"(a), "l"(b))
__device__ __forceinline__ u64 bcast2(float f) {
    u64 d; unsigned u = __float_as_uint(f);
    asm("mov.b64 %0, {%1, %1};" : "=l"(d) : "r"(u));
    return d;
}
__device__ __forceinline__ float2 unpack2(u64 p) {
    unsigned a, b;
    asm("mov.b64 {%0, %1}, %2;" : "=r"(a), "=r"(b) : "l"(p));
    return make_float2(__uint_as_float(a), __uint_as_float(b));
}

// ---------------------------------------------------------------------------
// small kernels
// ---------------------------------------------------------------------------
__global__ void init_kernel() { ((float*)g_psum)[threadIdx.x] = 0.f; }

__global__ __launch_bounds__(256) void wprep_kernel(
    const float* __restrict__ Wq, const float* __restrict__ Wk)
{
    const int i = blockIdx.x * 256 + threadIdx.x;      // 512 blocks -> 131072
    const int t = i >> 16, j = i & 65535;
    const float v  = (t ? Wk : Wq)[j];
    const float hi = wmma::__float_to_tf32(v);
    const float lo = wmma::__float_to_tf32(v - hi);
    g_Whi[t][j] = hi;
    g_Wlo[t][j] = lo;
}

__global__ void gn_finalize() {
    const int t = threadIdx.x;
    const int te = t >> 8, b = (t >> 5) & 7, g = t & 31;
    const float inv = 1.0f / (float)(CPG_ * HW_);
    float mu  = g_psum[te][b][g][0] * inv;
    float var = g_psum[te][b][g][1] * inv - mu * mu;
    g_stats[te][b][g] = make_float2(mu, rsqrtf(fmaxf(var, 0.f) + EPS_));
}

// ---------------------------------------------------------------------------
// Conv: WMMA tf32, 3xTF32 split, fp32 accumulators.
// CTA tile M=128(o) x N=128(s), K=256 in 8 chunks of 32.
// 8 warps as 4(M) x 2(N); warp tile 32x64 = 2x4 wmma 16x16x8 tiles.
// Dynamic smem (floats):
//   Ah [128][36] @0        Al [128][36] @4608
//   Bh [ 32][132] @9216    Bl [ 32][132] @13440    (total 17664 f = 70656 B)
// Epilogue reuses smem as staging [128][68] per N-half.
// ---------------------------------------------------------------------------
#define CONV_SMEM (17664 * 4)

__global__ __launch_bounds__(256, 2) void conv_tc_kernel(
    const float* __restrict__ X, int which)
{
    extern __shared__ __align__(16) float smf[];
    float* Ah = smf;
    float* Al = smf + 128 * 36;
    float* Bh = smf + 9216;
    float* Bl = smf + 13440;
    __shared__ float sg[16][2];

    float* __restrict__ Y = which ? g_Yk : g_Yq;
    const float* __restrict__ Whi = g_Whi[which];
    const float* __restrict__ Wlo = g_Wlo[which];

    const int tid = threadIdx.x;
    const int wid = tid >> 5;
    const int warp_m = wid & 3;          // 4 m-blocks of 32 rows
    const int warp_n = wid >> 2;         // 2 n-blocks of 64 cols
    const int o0 = blockIdx.x * 128;
    const int s0 = blockIdx.y * 128;
    const int b  = blockIdx.z;

    wmma::fragment<wmma::accumulator, 16, 16, 8, float> acc[2][4];
#pragma unroll
    for (int tm = 0; tm < 2; tm++)
#pragma unroll
        for (int tn = 0; tn < 4; tn++) wmma::fill_fragment(acc[tm][tn], 0.f);

    // loader coords
    const int arow = tid >> 1, ahalf = tid & 1;          // A: 2 thr/row, 16 f each
    const int brow = tid >> 3, bq = (tid & 7) * 16;      // B: 8 thr/row, 16 f each

    for (int ch = 0; ch < 8; ch++) {
        const int c0 = ch * 32;
        __syncthreads();                                  // prior compute done
        {
            const float* wh = Whi + (size_t)(o0 + arow) * C_ + c0 + ahalf * 16;
            const float* wl = Wlo + (size_t)(o0 + arow) * C_ + c0 + ahalf * 16;
#pragma unroll
            for (int j = 0; j < 4; j++) {
                *(float4*)&Ah[arow * 36 + ahalf * 16 + 4 * j] = *(const float4*)(wh + 4 * j);
                *(float4*)&Al[arow * 36 + ahalf * 16 + 4 * j] = *(const float4*)(wl + 4 * j);
            }
        }
        {
            const float* xr = X + ((size_t)b * C_ + c0 + brow) * HW_ + s0 + bq;
#pragma unroll
            for (int j = 0; j < 4; j++) {
                float4 v = *(const float4*)(xr + 4 * j);
                float4 h, l;
                h.x = wmma::__float_to_tf32(v.x); l.x = wmma::__float_to_tf32(v.x - h.x);
                h.y = wmma::__float_to_tf32(v.y); l.y = wmma::__float_to_tf32(v.y - h.y);
                h.z = wmma::__float_to_tf32(v.z); l.z = wmma::__float_to_tf32(v.z - h.z);
                h.w = wmma::__float_to_tf32(v.w); l.w = wmma::__float_to_tf32(v.w - h.w);
                *(float4*)&Bh[brow * 132 + bq + 4 * j] = h;
                *(float4*)&Bl[brow * 132 + bq + 4 * j] = l;
            }
        }
        __syncthreads();

#pragma unroll
        for (int t = 0; t < 4; t++) {
            wmma::fragment<wmma::matrix_a, 16, 16, 8, wmma::precision::tf32, wmma::row_major> ah[2], al[2];
#pragma unroll
            for (int tm = 0; tm < 2; tm++) {
                const int mrow = (warp_m * 32 + tm * 16) * 36 + t * 8;
                wmma::load_matrix_sync(ah[tm], &Ah[mrow], 36);
                wmma::load_matrix_sync(al[tm], &Al[mrow], 36);
            }
#pragma unroll
            for (int tn = 0; tn < 4; tn++) {
                wmma::fragment<wmma::matrix_b, 16, 16, 8, wmma::precision::tf32, wmma::row_major> bh, bl;
                const int boff = (t * 8) * 132 + warp_n * 64 + tn * 16;
                wmma::load_matrix_sync(bh, &Bh[boff], 132);
                wmma::load_matrix_sync(bl, &Bl[boff], 132);
#pragma unroll
                for (int tm = 0; tm < 2; tm++) {
                    wmma::mma_sync(acc[tm][tn], ah[tm], bl, acc[tm][tn]);
                    wmma::mma_sync(acc[tm][tn], al[tm], bh, acc[tm][tn]);
                    wmma::mma_sync(acc[tm][tn], ah[tm], bh, acc[tm][tn]);
                }
            }
        }
    }

    // epilogue in two N-halves, staging through smem, fused GN stats
    if (tid < 32) ((float*)sg)[tid] = 0.f;
#pragma unroll
    for (int h = 0; h < 2; h++) {
        __syncthreads();                                  // staging free to overwrite
        if (warp_n == h) {
#pragma unroll
            for (int tm = 0; tm < 2; tm++)
#pragma unroll
                for (int tn = 0; tn < 4; tn++)
                    wmma::store_matrix_sync(&smf[(warp_m * 32 + tm * 16) * 68 + tn * 16],
                                            acc[tm][tn], 68, wmma::mem_row_major);
        }
        __syncthreads();
        {
            const int row = tid >> 1, cq = (tid & 1) * 32;
            float* Yp = Y + ((size_t)b * C_ + o0 + row) * HW_ + s0 + h * 64 + cq;
            float s = 0.f, ss = 0.f;
#pragma unroll
            for (int j = 0; j < 8; j++) {
                float4 v = *(const float4*)&smf[row * 68 + cq + 4 * j];
                *(float4*)(Yp + 4 * j) = v;
                s  += v.x + v.y + v.z + v.w;
                ss += v.x * v.x + v.y * v.y + v.z * v.z + v.w * v.w;
            }
            atomicAdd(&sg[row >> 3][0], s);
            atomicAdd(&sg[row >> 3][1], ss);
        }
    }
    __syncthreads();
    if (tid < 32)
        atomicAdd(&g_psum[which][b][(o0 >> 3) + (tid >> 1)][tid & 1], sg[tid >> 1][tid & 1]);
}

// ---------------------------------------------------------------------------
// Kernel 3: per-patch attention (unchanged from best passing version)
// ---------------------------------------------------------------------------
#define ATTN_SMEM ((256 * AST + 2 * 32 * AST + 64 * AST) * 4)

__global__ __launch_bounds__(256, 2) void attn_kernel(
    const float* __restrict__ xlow,
    const float* __restrict__ gq, const float* __restrict__ bq,
    const float* __restrict__ gk, const float* __restrict__ bk,
    float* __restrict__ out)
{
    extern __shared__ __align__(16) float sm[];
    float* ks   = sm;
    float* bufQ = sm + 256 * AST;
    float* A    = sm + (256 + 64) * AST;

    const int n  = blockIdx.x;
    const int b  = n >> 8;
    const int ph = (n >> 4) & 15;
    const int pw = n & 15;
    const int tid = threadIdx.x;
    const size_t pbase = (size_t)b * C_ * HW_ + (size_t)(ph * 8) * W_ + pw * 8;

    const int cl = tid >> 3, il = tid & 7;
    const size_t lbase = pbase + (size_t)il * W_;

#pragma unroll
    for (int pass = 0; pass < 8; pass++) {
        const int c = pass * 32 + cl;
        const float2 st = g_stats[1][b][c >> 3];
        const float ak = st.y * __ldg(gk + c), ck = __ldg(bk + c) - st.x * ak;
        const float* src = g_Yk + lbase + (size_t)c * HW_;
        float4 v0 = *(const float4*)src;
        float4 v1 = *(const float4*)(src + 4);
        *(float4*)&ks[c * AST + il * 8]     = make_float4(v0.x*ak+ck, v0.y*ak+ck, v0.z*ak+ck, v0.w*ak+ck);
        *(float4*)&ks[c * AST + il * 8 + 4] = make_float4(v1.x*ak+ck, v1.y*ak+ck, v1.z*ak+ck, v1.w*ak+ck);
    }

    float4 q0, q1; float aq, cq;
    {
        const int c = cl;
        const float2 st = g_stats[0][b][c >> 3];
        aq = st.y * __ldg(gq + c); cq = __ldg(bq + c) - st.x * aq;
        const float* src = g_Yq + lbase + (size_t)c * HW_;
        q0 = *(const float4*)src; q1 = *(const float4*)(src + 4);
    }
    *(float4*)&bufQ[cl * AST + il * 8]     = make_float4(q0.x*aq+cq, q0.y*aq+cq, q0.z*aq+cq, q0.w*aq+cq);
    *(float4*)&bufQ[cl * AST + il * 8 + 4] = make_float4(q1.x*aq+cq, q1.y*aq+cq, q1.z*aq+cq, q1.w*aq+cq);
    __syncthreads();

    const int tx = tid & 15, ty = tid >> 4;
    u64 sacc[4][2];
#pragma unroll
    for (int m = 0; m < 4; m++) { sacc[m][0] = 0ull; sacc[m][1] = 0ull; }

    for (int ch = 0; ch < 8; ch++) {
        const int buf = ch & 1;
        if (ch < 7) {
            const int c = (ch + 1) * 32 + cl;
            const float2 st = g_stats[0][b][c >> 3];
            aq = st.y * __ldg(gq + c); cq = __ldg(bq + c) - st.x * aq;
            const float* src = g_Yq + lbase + (size_t)c * HW_;
            q0 = *(const float4*)src; q1 = *(const float4*)(src + 4);
        }
        const float* bq_ = bufQ + buf * 32 * AST + 4 * ty;
        const float* ks_ = ks + (ch * 32) * AST + 4 * tx;
#pragma unroll 4
        for (int cc = 0; cc < 32; cc++) {
            float4 qv = *(const float4*)(bq_ + cc * AST);
            ulonglong2 kv = *(const ulonglong2*)(ks_ + cc * AST);
            u64 qp0 = bcast2(qv.x), qp1 = bcast2(qv.y), qp2 = bcast2(qv.z), qp3 = bcast2(qv.w);
            FMA2(sacc[0][0], qp0, kv.x); FMA2(sacc[0][1], qp0, kv.y);
            FMA2(sacc[1][0], qp1, kv.x); FMA2(sacc[1][1], qp1, kv.y);
            FMA2(sacc[2][0], qp2, kv.x); FMA2(sacc[2][1], qp2, kv.y);
            FMA2(sacc[3][0], qp3, kv.x); FMA2(sacc[3][1], qp3, kv.y);
        }
        if (ch < 7) {
            __syncthreads();
            const int nb = buf ^ 1;
            *(float4*)&bufQ[nb * 32 * AST + cl * AST + il * 8]     = make_float4(q0.x*aq+cq, q0.y*aq+cq, q0.z*aq+cq, q0.w*aq+cq);
            *(float4*)&bufQ[nb * 32 * AST + cl * AST + il * 8 + 4] = make_float4(q1.x*aq+cq, q1.y*aq+cq, q1.z*aq+cq, q1.w*aq+cq);
            __syncthreads();
        }
    }
#pragma unroll
    for (int m = 0; m < 4; m++)
        *(ulonglong2*)&A[(4 * ty + m) * AST + 4 * tx] = make_ulonglong2(sacc[m][0], sacc[m][1]);
    __syncthreads();

    {
        float* row = A + (tid >> 2) * AST + (tid & 3) * 16;
        float mx = -1e30f;
#pragma unroll
        for (int j = 0; j < 16; j++) mx = fmaxf(mx, row[j] * 0.0625f);
        mx = fmaxf(mx, __shfl_xor_sync(0xffffffffu, mx, 1));
        mx = fmaxf(mx, __shfl_xor_sync(0xffffffffu, mx, 2));
        float s = 0.f;
#pragma unroll
        for (int j = 0; j < 16; j++) { float e = __expf(row[j] * 0.0625f - mx); row[j] = e; s += e; }
        s += __shfl_xor_sync(0xffffffffu, s, 1);
        s += __shfl_xor_sync(0xffffffffu, s, 2);
        const float inv = 1.0f / s;
#pragma unroll
        for (int j = 0; j < 16; j++) row[j] *= inv;
    }
    __syncthreads();

    const int pg = tid & 7, cg = tid >> 3;
#pragma unroll 1
    for (int h = 0; h < 2; h++) {
        u64 oacc[8][4];
#pragma unroll
        for (int jp = 0; jp < 8; jp++)
#pragma unroll
            for (int jc = 0; jc < 4; jc++) oacc[jp][jc] = 0ull;

        const float* kb = ks + (h * 128 + cg) * AST;
#pragma unroll 4
        for (int ppb = 0; ppb < 16; ppb++) {
            ulonglong2 ap[8];
#pragma unroll
            for (int jp = 0; jp < 8; jp++)
                ap[jp] = *(const ulonglong2*)&A[(pg + 8 * jp) * AST + 4 * ppb];
#pragma unroll
            for (int jc = 0; jc < 4; jc++) {
                ulonglong2 kp = *(const ulonglong2*)(kb + jc * 32 * AST + 4 * ppb);
#pragma unroll
                for (int jp = 0; jp < 8; jp++) {
                    FMA2(oacc[jp][jc], ap[jp].x, kp.x);
                    FMA2(oacc[jp][jc], ap[jp].y, kp.y);
                }
            }
        }
#pragma unroll
        for (int jc = 0; jc < 4; jc++) {
            const int c = h * 128 + cg + 32 * jc;
            const size_t cb = pbase + (size_t)c * HW_ + pg;
#pragma unroll
            for (int jp = 0; jp < 8; jp++) {
                float2 v = unpack2(oacc[jp][jc]);
                const size_t off = cb + (size_t)jp * W_;
                out[off] = v.x + v.y + __ldg(xlow + off);
            }
        }
    }
}

// ---------------------------------------------------------------------------
// Launch
// ---------------------------------------------------------------------------
extern "C" void kernel_launch(void* const* d_in, const int* in_sizes, int n_in,
                              void* d_out, int out_size)
{
    const float* x_low  = (const float*)d_in[0];
    const float* x_high = (const float*)d_in[1];
    const float* Wq     = (const float*)d_in[2];
    const float* gq     = (const float*)d_in[3];
    const float* bq     = (const float*)d_in[4];
    const float* Wk     = (const float*)d_in[5];
    const float* gk     = (const float*)d_in[6];
    const float* bk     = (const float*)d_in[7];
    float* out = (float*)d_out;

    cudaFuncSetAttribute(conv_tc_kernel, cudaFuncAttributeMaxDynamicSharedMemorySize, CONV_SMEM);
    cudaFuncSetAttribute(attn_kernel, cudaFuncAttributeMaxDynamicSharedMemorySize, ATTN_SMEM);

    init_kernel<<<1, 1024>>>();
    wprep_kernel<<<512, 256>>>(Wq, Wk);

    dim3 cgrid(2, 128, 8);   // o-tiles fastest -> X tile L2 reuse between twins
    conv_tc_kernel<<<cgrid, 256, CONV_SMEM>>>(x_low,  0);
    conv_tc_kernel<<<cgrid, 256, CONV_SMEM>>>(x_high, 1);
    gn_finalize<<<1, 512>>>();
    attn_kernel<<<2048, 256, ATTN_SMEM>>>(x_low, gq, bq, gk, bk, out);
}

// round 13
// speedup vs baseline: 1.7590x; 1.7590x over previous
#include <cuda_runtime.h>
#include <cuda_bf16.h>
#include <cstdint>
#include <mma.h>

using namespace nvcuda;

#define B_      8
#define C_      256
#define H_      128
#define W_      128
#define HW_     (H_ * W_)
#define GROUPS_ 32
#define CPG_    8
#define EPS_    1e-5f
#define AST     68

typedef unsigned long long u64;
typedef __nv_bfloat16 bf16;

// ---------------------------------------------------------------------------
// Scratch
// ---------------------------------------------------------------------------
__device__ float  g_Yq[(size_t)B_ * C_ * HW_];
__device__ float  g_Yk[(size_t)B_ * C_ * HW_];
__device__ __align__(16) bf16 g_Wbh[2][C_ * C_];   // bf16(v)
__device__ __align__(16) bf16 g_Wbl[2][C_ * C_];   // bf16(v - hi)
__device__ float  g_psum[2][B_][GROUPS_][2];
__device__ float2 g_stats[2][B_][GROUPS_];

// ---------------------------------------------------------------------------
// fp32x2 helpers (attn kernel)
// ---------------------------------------------------------------------------
#define FMA2(acc, a, b) asm("fma.rn.f32x2 %0, %1, %2, %0;" : "+l"(acc) : "l"(a), "l"(b))
__device__ __forceinline__ u64 bcast2(float f) {
    u64 d; unsigned u = __float_as_uint(f);
    asm("mov.b64 %0, {%1, %1};" : "=l"(d) : "r"(u));
    return d;
}
__device__ __forceinline__ float2 unpack2(u64 p) {
    unsigned a, b;
    asm("mov.b64 {%0, %1}, %2;" : "=r"(a), "=r"(b) : "l"(p));
    return make_float2(__uint_as_float(a), __uint_as_float(b));
}

// ---------------------------------------------------------------------------
// small kernels
// ---------------------------------------------------------------------------
__global__ void init_kernel() { ((float*)g_psum)[threadIdx.x] = 0.f; }

__global__ __launch_bounds__(256) void wprep_kernel(
    const float* __restrict__ Wq, const float* __restrict__ Wk)
{
    const int i = blockIdx.x * 256 + threadIdx.x;      // 512 blocks -> 131072
    const int t = i >> 16, j = i & 65535;
    const float v  = (t ? Wk : Wq)[j];
    const bf16 hi = __float2bfloat16_rn(v);
    const bf16 lo = __float2bfloat16_rn(v - __bfloat162float(hi));
    g_Wbh[t][j] = hi;
    g_Wbl[t][j] = lo;
}

__global__ void gn_finalize() {
    const int t = threadIdx.x;
    const int te = t >> 8, b = (t >> 5) & 7, g = t & 31;
    const float inv = 1.0f / (float)(CPG_ * HW_);
    float mu  = g_psum[te][b][g][0] * inv;
    float var = g_psum[te][b][g][1] * inv - mu * mu;
    g_stats[te][b][g] = make_float2(mu, rsqrtf(fmaxf(var, 0.f) + EPS_));
}

// ---------------------------------------------------------------------------
// Conv: WMMA bf16 m16n16k16, UNscaled 3-term split (hi*hi + hi*lo + lo*hi)
// into a SINGLE fp32 accumulator. CTA 512 thr, tile M=128(o) x N=128(s),
// K=256 in 8 chunks of 32. 16 warps as 4(M) x 4(N), warp tile 32x32.
// Epilogue stages D in TWO 64-column halves through stg[128][68]
// (the R11/R12 bug was staging 128 columns into a 68-stride buffer).
// smem (bf16): Ah[128][40] Al[128][40] Bh[32][136] Bl[32][136] = 18944 el
//   = 37888 B. Staging [128][68] f32 = 34816 B reuses it.
// ---------------------------------------------------------------------------
#define OFF_AL  5120
#define OFF_BH  10240
#define OFF_BL  14592
#define CONV_SMEM (18944 * 2)

using FragA = wmma::fragment<wmma::matrix_a, 16, 16, 16, bf16, wmma::row_major>;
using FragB = wmma::fragment<wmma::matrix_b, 16, 16, 16, bf16, wmma::row_major>;
using FragC = wmma::fragment<wmma::accumulator, 16, 16, 16, float>;

__global__ __launch_bounds__(512, 1) void conv_tc_kernel(
    const float* __restrict__ X0, const float* __restrict__ X1)
{
    extern __shared__ __align__(16) bf16 smh[];
    __shared__ float sg[16][2];

    const int tid = threadIdx.x;
    const int wid = tid >> 5;
    const int warp_m = wid & 3;           // 4 m-blocks of 32 rows (o)
    const int warp_n = wid >> 2;          // 4 n-blocks of 32 cols (s)
    const int o0 = blockIdx.x * 128;
    const int s0 = blockIdx.y * 128;
    const int which = blockIdx.z >> 3;
    const int b  = blockIdx.z & 7;

    const float*  X  = which ? X1 : X0;
    float* __restrict__ Y = which ? g_Yk : g_Yq;
    const bf16* Wbh = g_Wbh[which];
    const bf16* Wbl = g_Wbl[which];

    FragC acc[2][2];
#pragma unroll
    for (int tm = 0; tm < 2; tm++)
#pragma unroll
        for (int tn = 0; tn < 2; tn++) wmma::fill_fragment(acc[tm][tn], 0.f);

    // loader coords
    const int wrow = tid >> 2, wseg = (tid & 3) * 8;      // W: 4 thr/row, 8 bf16 each
    const int xrow = tid >> 4, xseg = (tid & 15) * 8;     // X: 16 thr/row, 8 floats each

    uint4 whv, wlv;
    float xv[8];
    {
        whv = *(const uint4*)&Wbh[(size_t)(o0 + wrow) * C_ + wseg];
        wlv = *(const uint4*)&Wbl[(size_t)(o0 + wrow) * C_ + wseg];
        const float* xp = X + ((size_t)b * C_ + xrow) * HW_ + s0 + xseg;
        *(float4*)&xv[0] = *(const float4*)xp;
        *(float4*)&xv[4] = *(const float4*)(xp + 4);
    }
    // store chunk 0
    {
        *(uint4*)&smh[wrow * 40 + wseg]          = whv;
        *(uint4*)&smh[OFF_AL + wrow * 40 + wseg] = wlv;
        __align__(16) bf16 hh[8], ll[8];
#pragma unroll
        for (int j = 0; j < 8; j++) {
            hh[j] = __float2bfloat16_rn(xv[j]);
            ll[j] = __float2bfloat16_rn(xv[j] - __bfloat162float(hh[j]));
        }
        *(uint4*)&smh[OFF_BH + xrow * 136 + xseg] = *(uint4*)hh;
        *(uint4*)&smh[OFF_BL + xrow * 136 + xseg] = *(uint4*)ll;
    }
    if (tid < 32) ((float*)sg)[tid] = 0.f;
    __syncthreads();

    for (int ch = 0; ch < 8; ch++) {
        if (ch < 7) {   // prefetch next chunk into regs (hides DRAM under compute)
            const int c0 = (ch + 1) * 32;
            whv = *(const uint4*)&Wbh[(size_t)(o0 + wrow) * C_ + c0 + wseg];
            wlv = *(const uint4*)&Wbl[(size_t)(o0 + wrow) * C_ + c0 + wseg];
            const float* xp = X + ((size_t)b * C_ + c0 + xrow) * HW_ + s0 + xseg;
            *(float4*)&xv[0] = *(const float4*)xp;
            *(float4*)&xv[4] = *(const float4*)(xp + 4);
        }

#pragma unroll
        for (int t = 0; t < 2; t++) {
            FragA ah[2], al[2];
#pragma unroll
            for (int tm = 0; tm < 2; tm++) {
                const int ao = (warp_m * 32 + tm * 16) * 40 + t * 16;
                wmma::load_matrix_sync(ah[tm], smh + ao, 40);
                wmma::load_matrix_sync(al[tm], smh + OFF_AL + ao, 40);
            }
#pragma unroll
            for (int tn = 0; tn < 2; tn++) {
                FragB bh, bl;
                const int bo = (t * 16) * 136 + warp_n * 32 + tn * 16;
                wmma::load_matrix_sync(bh, smh + OFF_BH + bo, 136);
                wmma::load_matrix_sync(bl, smh + OFF_BL + bo, 136);
#pragma unroll
                for (int tm = 0; tm < 2; tm++) {
                    wmma::mma_sync(acc[tm][tn], ah[tm], bh, acc[tm][tn]);
                    wmma::mma_sync(acc[tm][tn], ah[tm], bl, acc[tm][tn]);
                    wmma::mma_sync(acc[tm][tn], al[tm], bh, acc[tm][tn]);
                }
            }
        }

        if (ch < 7) {
            __syncthreads();   // all warps done reading current chunk
            *(uint4*)&smh[wrow * 40 + wseg]          = whv;
            *(uint4*)&smh[OFF_AL + wrow * 40 + wseg] = wlv;
            __align__(16) bf16 hh[8], ll[8];
#pragma unroll
            for (int j = 0; j < 8; j++) {
                hh[j] = __float2bfloat16_rn(xv[j]);
                ll[j] = __float2bfloat16_rn(xv[j] - __bfloat162float(hh[j]));
            }
            *(uint4*)&smh[OFF_BH + xrow * 136 + xseg] = *(uint4*)hh;
            *(uint4*)&smh[OFF_BL + xrow * 136 + xseg] = *(uint4*)ll;
            __syncthreads();   // stores visible before next compute
        }
    }

    // ---- epilogue in TWO 64-column halves (fix for the stride-68 aliasing) ----
    float* stg = (float*)smh;          // [128][68] f32 staging
    float s = 0.f, ss = 0.f;
    const int row = tid >> 2, cq = (tid & 3) * 16;   // 128 rows x 4 segs of 16
#pragma unroll
    for (int h = 0; h < 2; h++) {
        __syncthreads();               // operand smem / previous half free
        if ((warp_n >> 1) == h) {
#pragma unroll
            for (int tm = 0; tm < 2; tm++)
#pragma unroll
                for (int tn = 0; tn < 2; tn++)
                    wmma::store_matrix_sync(
                        &stg[(warp_m * 32 + tm * 16) * 68 + (warp_n & 1) * 32 + tn * 16],
                        acc[tm][tn], 68, wmma::mem_row_major);
        }
        __syncthreads();
        float* Yp = Y + ((size_t)b * C_ + o0 + row) * HW_ + s0 + h * 64 + cq;
#pragma unroll
        for (int j = 0; j < 4; j++) {
            float4 v = *(const float4*)&stg[row * 68 + cq + 4 * j];
            *(float4*)(Yp + 4 * j) = v;
            s  += v.x + v.y + v.z + v.w;
            ss += v.x * v.x + v.y * v.y + v.z * v.z + v.w * v.w;
        }
    }
    atomicAdd(&sg[row >> 3][0], s);
    atomicAdd(&sg[row >> 3][1], ss);
    __syncthreads();
    if (tid < 32)
        atomicAdd(&g_psum[which][b][(o0 >> 3) + (tid >> 1)][tid & 1], sg[tid >> 1][tid & 1]);
}

// ---------------------------------------------------------------------------
// Kernel 3: per-patch attention (unchanged from best passing version)
// ---------------------------------------------------------------------------
#define ATTN_SMEM ((256 * AST + 2 * 32 * AST + 64 * AST) * 4)

__global__ __launch_bounds__(256, 2) void attn_kernel(
    const float* __restrict__ xlow,
    const float* __restrict__ gq, const float* __restrict__ bq,
    const float* __restrict__ gk, const float* __restrict__ bk,
    float* __restrict__ out)
{
    extern __shared__ __align__(16) float sm[];
    float* ks   = sm;
    float* bufQ = sm + 256 * AST;
    float* A    = sm + (256 + 64) * AST;

    const int n  = blockIdx.x;
    const int b  = n >> 8;
    const int ph = (n >> 4) & 15;
    const int pw = n & 15;
    const int tid = threadIdx.x;
    const size_t pbase = (size_t)b * C_ * HW_ + (size_t)(ph * 8) * W_ + pw * 8;

    const int cl = tid >> 3, il = tid & 7;
    const size_t lbase = pbase + (size_t)il * W_;

#pragma unroll
    for (int pass = 0; pass < 8; pass++) {
        const int c = pass * 32 + cl;
        const float2 st = g_stats[1][b][c >> 3];
        const float ak = st.y * __ldg(gk + c), ck = __ldg(bk + c) - st.x * ak;
        const float* src = g_Yk + lbase + (size_t)c * HW_;
        float4 v0 = *(const float4*)src;
        float4 v1 = *(const float4*)(src + 4);
        *(float4*)&ks[c * AST + il * 8]     = make_float4(v0.x*ak+ck, v0.y*ak+ck, v0.z*ak+ck, v0.w*ak+ck);
        *(float4*)&ks[c * AST + il * 8 + 4] = make_float4(v1.x*ak+ck, v1.y*ak+ck, v1.z*ak+ck, v1.w*ak+ck);
    }

    float4 q0, q1; float aq, cq;
    {
        const int c = cl;
        const float2 st = g_stats[0][b][c >> 3];
        aq = st.y * __ldg(gq + c); cq = __ldg(bq + c) - st.x * aq;
        const float* src = g_Yq + lbase + (size_t)c * HW_;
        q0 = *(const float4*)src; q1 = *(const float4*)(src + 4);
    }
    *(float4*)&bufQ[cl * AST + il * 8]     = make_float4(q0.x*aq+cq, q0.y*aq+cq, q0.z*aq+cq, q0.w*aq+cq);
    *(float4*)&bufQ[cl * AST + il * 8 + 4] = make_float4(q1.x*aq+cq, q1.y*aq+cq, q1.z*aq+cq, q1.w*aq+cq);
    __syncthreads();

    const int tx = tid & 15, ty = tid >> 4;
    u64 sacc[4][2];
#pragma unroll
    for (int m = 0; m < 4; m++) { sacc[m][0] = 0ull; sacc[m][1] = 0ull; }

    for (int ch = 0; ch < 8; ch++) {
        const int buf = ch & 1;
        if (ch < 7) {
            const int c = (ch + 1) * 32 + cl;
            const float2 st = g_stats[0][b][c >> 3];
            aq = st.y * __ldg(gq + c); cq = __ldg(bq + c) - st.x * aq;
            const float* src = g_Yq + lbase + (size_t)c * HW_;
            q0 = *(const float4*)src; q1 = *(const float4*)(src + 4);
        }
        const float* bq_ = bufQ + buf * 32 * AST + 4 * ty;
        const float* ks_ = ks + (ch * 32) * AST + 4 * tx;
#pragma unroll 4
        for (int cc = 0; cc < 32; cc++) {
            float4 qv = *(const float4*)(bq_ + cc * AST);
            ulonglong2 kv = *(const ulonglong2*)(ks_ + cc * AST);
            u64 qp0 = bcast2(qv.x), qp1 = bcast2(qv.y), qp2 = bcast2(qv.z), qp3 = bcast2(qv.w);
            FMA2(sacc[0][0], qp0, kv.x); FMA2(sacc[0][1], qp0, kv.y);
            FMA2(sacc[1][0], qp1, kv.x); FMA2(sacc[1][1], qp1, kv.y);
            FMA2(sacc[2][0], qp2, kv.x); FMA2(sacc[2][1], qp2, kv.y);
            FMA2(sacc[3][0], qp3, kv.x); FMA2(sacc[3][1], qp3, kv.y);
        }
        if (ch < 7) {
            __syncthreads();
            const int nb = buf ^ 1;
            *(float4*)&bufQ[nb * 32 * AST + cl * AST + il * 8]     = make_float4(q0.x*aq+cq, q0.y*aq+cq, q0.z*aq+cq, q0.w*aq+cq);
            *(float4*)&bufQ[nb * 32 * AST + cl * AST + il * 8 + 4] = make_float4(q1.x*aq+cq, q1.y*aq+cq, q1.z*aq+cq, q1.w*aq+cq);
            __syncthreads();
        }
    }
#pragma unroll
    for (int m = 0; m < 4; m++)
        *(ulonglong2*)&A[(4 * ty + m) * AST + 4 * tx] = make_ulonglong2(sacc[m][0], sacc[m][1]);
    __syncthreads();

    {
        float* row = A + (tid >> 2) * AST + (tid & 3) * 16;
        float mx = -1e30f;
#pragma unroll
        for (int j = 0; j < 16; j++) mx = fmaxf(mx, row[j] * 0.0625f);
        mx = fmaxf(mx, __shfl_xor_sync(0xffffffffu, mx, 1));
        mx = fmaxf(mx, __shfl_xor_sync(0xffffffffu, mx, 2));
        float s = 0.f;
#pragma unroll
        for (int j = 0; j < 16; j++) { float e = __expf(row[j] * 0.0625f - mx); row[j] = e; s += e; }
        s += __shfl_xor_sync(0xffffffffu, s, 1);
        s += __shfl_xor_sync(0xffffffffu, s, 2);
        const float inv = 1.0f / s;
#pragma unroll
        for (int j = 0; j < 16; j++) row[j] *= inv;
    }
    __syncthreads();

    const int pg = tid & 7, cg = tid >> 3;
#pragma unroll 1
    for (int h = 0; h < 2; h++) {
        u64 oacc[8][4];
#pragma unroll
        for (int jp = 0; jp < 8; jp++)
#pragma unroll
            for (int jc = 0; jc < 4; jc++) oacc[jp][jc] = 0ull;

        const float* kb = ks + (h * 128 + cg) * AST;
#pragma unroll 4
        for (int ppb = 0; ppb < 16; ppb++) {
            ulonglong2 ap[8];
#pragma unroll
            for (int jp = 0; jp < 8; jp++)
                ap[jp] = *(const ulonglong2*)&A[(pg + 8 * jp) * AST + 4 * ppb];
#pragma unroll
            for (int jc = 0; jc < 4; jc++) {
                ulonglong2 kp = *(const ulonglong2*)(kb + jc * 32 * AST + 4 * ppb);
#pragma unroll
                for (int jp = 0; jp < 8; jp++) {
                    FMA2(oacc[jp][jc], ap[jp].x, kp.x);
                    FMA2(oacc[jp][jc], ap[jp].y, kp.y);
                }
            }
        }
#pragma unroll
        for (int jc = 0; jc < 4; jc++) {
            const int c = h * 128 + cg + 32 * jc;
            const size_t cb = pbase + (size_t)c * HW_ + pg;
#pragma unroll
            for (int jp = 0; jp < 8; jp++) {
                float2 v = unpack2(oacc[jp][jc]);
                const size_t off = cb + (size_t)jp * W_;
                out[off] = v.x + v.y + __ldg(xlow + off);
            }
        }
    }
}

// ---------------------------------------------------------------------------
// Launch
// ---------------------------------------------------------------------------
extern "C" void kernel_launch(void* const* d_in, const int* in_sizes, int n_in,
                              void* d_out, int out_size)
{
    const float* x_low  = (const float*)d_in[0];
    const float* x_high = (const float*)d_in[1];
    const float* Wq     = (const float*)d_in[2];
    const float* gq     = (const float*)d_in[3];
    const float* bq     = (const float*)d_in[4];
    const float* Wk     = (const float*)d_in[5];
    const float* gk     = (const float*)d_in[6];
    const float* bk     = (const float*)d_in[7];
    float* out = (float*)d_out;

    cudaFuncSetAttribute(conv_tc_kernel, cudaFuncAttributeMaxDynamicSharedMemorySize, CONV_SMEM);
    cudaFuncSetAttribute(attn_kernel, cudaFuncAttributeMaxDynamicSharedMemorySize, ATTN_SMEM);

    init_kernel<<<1, 1024>>>();
    wprep_kernel<<<512, 256>>>(Wq, Wk);

    // both convs in one launch; x fastest so o-twins share the X tile in L2
    conv_tc_kernel<<<dim3(2, 128, 16), 512, CONV_SMEM>>>(x_low, x_high);
    gn_finalize<<<1, 512>>>();
    attn_kernel<<<2048, 256, ATTN_SMEM>>>(x_low, gq, bq, gk, bk, out);
}

// round 15
// speedup vs baseline: 1.8872x; 1.0729x over previous
#include <cuda_runtime.h>
#include <cuda_bf16.h>
#include <cstdint>
#include <mma.h>

using namespace nvcuda;

#define B_      8
#define C_      256
#define H_      128
#define W_      128
#define HW_     (H_ * W_)
#define GROUPS_ 32
#define CPG_    8
#define EPS_    1e-5f
#define AST     68

typedef unsigned long long u64;
typedef __nv_bfloat16 bf16;

// ---------------------------------------------------------------------------
// Scratch
// ---------------------------------------------------------------------------
__device__ float  g_Yq[(size_t)B_ * C_ * HW_];
__device__ float  g_Yk[(size_t)B_ * C_ * HW_];
__device__ __align__(16) bf16 g_Wbh[2][C_ * C_];   // bf16(v)
__device__ __align__(16) bf16 g_Wbl[2][C_ * C_];   // bf16(v - hi)
__device__ float  g_psum[2][B_][GROUPS_][2];
__device__ float2 g_stats[2][B_][GROUPS_];

// ---------------------------------------------------------------------------
// fp32x2 helpers (attn kernel)
// ---------------------------------------------------------------------------
#define FMA2(acc, a, b) asm("fma.rn.f32x2 %0, %1, %2, %0;" : "+l"(acc) : "l"(a), "l"(b))
__device__ __forceinline__ u64 bcast2(float f) {
    u64 d; unsigned u = __float_as_uint(f);
    asm("mov.b64 %0, {%1, %1};" : "=l"(d) : "r"(u));
    return d;
}
__device__ __forceinline__ float2 unpack2(u64 p) {
    unsigned a, b;
    asm("mov.b64 {%0, %1}, %2;" : "=r"(a), "=r"(b) : "l"(p));
    return make_float2(__uint_as_float(a), __uint_as_float(b));
}

// ---------------------------------------------------------------------------
// small kernels
// ---------------------------------------------------------------------------
__global__ void init_kernel() { ((float*)g_psum)[threadIdx.x] = 0.f; }

__global__ __launch_bounds__(256) void wprep_kernel(
    const float* __restrict__ Wq, const float* __restrict__ Wk)
{
    const int i = blockIdx.x * 256 + threadIdx.x;      // 512 blocks -> 131072
    const int t = i >> 16, j = i & 65535;
    const float v  = (t ? Wk : Wq)[j];
    const bf16 hi = __float2bfloat16_rn(v);
    const bf16 lo = __float2bfloat16_rn(v - __bfloat162float(hi));
    g_Wbh[t][j] = hi;
    g_Wbl[t][j] = lo;
}

__global__ void gn_finalize() {
    const int t = threadIdx.x;
    const int te = t >> 8, b = (t >> 5) & 7, g = t & 31;
    const float inv = 1.0f / (float)(CPG_ * HW_);
    float mu  = g_psum[te][b][g][0] * inv;
    float var = g_psum[te][b][g][1] * inv - mu * mu;
    g_stats[te][b][g] = make_float2(mu, rsqrtf(fmaxf(var, 0.f) + EPS_));
}

// ---------------------------------------------------------------------------
// Conv: WMMA bf16 m16n16k16, UNscaled 3-term split (hi*hi + hi*lo + lo*hi)
// into a SINGLE fp32 accumulator. CTA 512 thr, tile M=128(o) x N=128(s),
// K=256 in 8 chunks of 32. 16 warps as 4(M) x 4(N), warp tile 32x32.
// DOUBLE-BUFFERED smem: one __syncthreads per chunk; next-chunk split+STS
// overlaps current-chunk MMA. Safety: stores in iter ch target buf[cur^1],
// whose last readers (iter ch-1) passed the end-of-iter barrier.
// Per stage (bf16): Ah[128][40] Al[128][40] Bh[32][136] Bl[32][136]
//   = 18944 el = 37888 B; x2 stages = 75776 B.
// Epilogue stages D in TWO 64-column halves through stg[128][68] (34816 B).
// ---------------------------------------------------------------------------
#define OFF_AL  5120
#define OFF_BH  10240
#define OFF_BL  14592
#define STG_EL  18944
#define CONV_SMEM (STG_EL * 2 * 2)

using FragA = wmma::fragment<wmma::matrix_a, 16, 16, 16, bf16, wmma::row_major>;
using FragB = wmma::fragment<wmma::matrix_b, 16, 16, 16, bf16, wmma::row_major>;
using FragC = wmma::fragment<wmma::accumulator, 16, 16, 16, float>;

__global__ __launch_bounds__(512, 1) void conv_tc_kernel(
    const float* __restrict__ X0, const float* __restrict__ X1)
{
    extern __shared__ __align__(16) bf16 smh[];
    __shared__ float sg[16][2];

    const int tid = threadIdx.x;
    const int wid = tid >> 5;
    const int warp_m = wid & 3;           // 4 m-blocks of 32 rows (o)
    const int warp_n = wid >> 2;          // 4 n-blocks of 32 cols (s)
    const int o0 = blockIdx.x * 128;
    const int s0 = blockIdx.y * 128;
    const int which = blockIdx.z >> 3;
    const int b  = blockIdx.z & 7;

    const float*  X  = which ? X1 : X0;
    float* __restrict__ Y = which ? g_Yk : g_Yq;
    const bf16* Wbh = g_Wbh[which];
    const bf16* Wbl = g_Wbl[which];

    FragC acc[2][2];
#pragma unroll
    for (int tm = 0; tm < 2; tm++)
#pragma unroll
        for (int tn = 0; tn < 2; tn++) wmma::fill_fragment(acc[tm][tn], 0.f);

    // loader coords
    const int wrow = tid >> 2, wseg = (tid & 3) * 8;      // W: 4 thr/row, 8 bf16 each
    const int xrow = tid >> 4, xseg = (tid & 15) * 8;     // X: 16 thr/row, 8 floats each

    uint4 whv, wlv;
    float xv[8];
    {
        whv = *(const uint4*)&Wbh[(size_t)(o0 + wrow) * C_ + wseg];
        wlv = *(const uint4*)&Wbl[(size_t)(o0 + wrow) * C_ + wseg];
        const float* xp = X + ((size_t)b * C_ + xrow) * HW_ + s0 + xseg;
        *(float4*)&xv[0] = *(const float4*)xp;
        *(float4*)&xv[4] = *(const float4*)(xp + 4);
    }
    // store chunk 0 into buffer 0
    {
        *(uint4*)&smh[wrow * 40 + wseg]          = whv;
        *(uint4*)&smh[OFF_AL + wrow * 40 + wseg] = wlv;
        __align__(16) bf16 hh[8], ll[8];
#pragma unroll
        for (int j = 0; j < 8; j++) {
            hh[j] = __float2bfloat16_rn(xv[j]);
            ll[j] = __float2bfloat16_rn(xv[j] - __bfloat162float(hh[j]));
        }
        *(uint4*)&smh[OFF_BH + xrow * 136 + xseg] = *(uint4*)hh;
        *(uint4*)&smh[OFF_BL + xrow * 136 + xseg] = *(uint4*)ll;
    }
    if (tid < 32) ((float*)sg)[tid] = 0.f;
    __syncthreads();

    for (int ch = 0; ch < 8; ch++) {
        const bf16* cb = smh + (ch & 1) * STG_EL;

        if (ch < 7) {   // prefetch next chunk into regs (overlaps MMA below)
            const int c0 = (ch + 1) * 32;
            whv = *(const uint4*)&Wbh[(size_t)(o0 + wrow) * C_ + c0 + wseg];
            wlv = *(const uint4*)&Wbl[(size_t)(o0 + wrow) * C_ + c0 + wseg];
            const float* xp = X + ((size_t)b * C_ + c0 + xrow) * HW_ + s0 + xseg;
            *(float4*)&xv[0] = *(const float4*)xp;
            *(float4*)&xv[4] = *(const float4*)(xp + 4);
        }

#pragma unroll
        for (int t = 0; t < 2; t++) {
            FragA ah[2], al[2];
#pragma unroll
            for (int tm = 0; tm < 2; tm++) {
                const int ao = (warp_m * 32 + tm * 16) * 40 + t * 16;
                wmma::load_matrix_sync(ah[tm], cb + ao, 40);
                wmma::load_matrix_sync(al[tm], cb + OFF_AL + ao, 40);
            }
#pragma unroll
            for (int tn = 0; tn < 2; tn++) {
                FragB bh, bl;
                const int bo = (t * 16) * 136 + warp_n * 32 + tn * 16;
                wmma::load_matrix_sync(bh, cb + OFF_BH + bo, 136);
                wmma::load_matrix_sync(bl, cb + OFF_BL + bo, 136);
#pragma unroll
                for (int tm = 0; tm < 2; tm++) {
                    wmma::mma_sync(acc[tm][tn], ah[tm], bh, acc[tm][tn]);
                    wmma::mma_sync(acc[tm][tn], ah[tm], bl, acc[tm][tn]);
                    wmma::mma_sync(acc[tm][tn], al[tm], bh, acc[tm][tn]);
                }
            }
        }

        if (ch < 7) {   // store next chunk into the OTHER buffer (no pre-sync needed)
            bf16* nb = smh + ((ch + 1) & 1) * STG_EL;
            *(uint4*)&nb[wrow * 40 + wseg]          = whv;
            *(uint4*)&nb[OFF_AL + wrow * 40 + wseg] = wlv;
            __align__(16) bf16 hh[8], ll[8];
#pragma unroll
            for (int j = 0; j < 8; j++) {
                hh[j] = __float2bfloat16_rn(xv[j]);
                ll[j] = __float2bfloat16_rn(xv[j] - __bfloat162float(hh[j]));
            }
            *(uint4*)&nb[OFF_BH + xrow * 136 + xseg] = *(uint4*)hh;
            *(uint4*)&nb[OFF_BL + xrow * 136 + xseg] = *(uint4*)ll;
        }
        __syncthreads();   // single barrier per chunk
    }

    // ---- epilogue in TWO 64-column halves (stride-68 staging, proven in R13) ----
    float* stg = (float*)smh;          // [128][68] f32 staging (reuses buffer 0)
    float s = 0.f, ss = 0.f;
    const int row = tid >> 2, cq = (tid & 3) * 16;   // 128 rows x 4 segs of 16
#pragma unroll
    for (int h = 0; h < 2; h++) {
        __syncthreads();               // staging region free
        if ((warp_n >> 1) == h) {
#pragma unroll
            for (int tm = 0; tm < 2; tm++)
#pragma unroll
                for (int tn = 0; tn < 2; tn++)
                    wmma::store_matrix_sync(
                        &stg[(warp_m * 32 + tm * 16) * 68 + (warp_n & 1) * 32 + tn * 16],
                        acc[tm][tn], 68, wmma::mem_row_major);
        }
        __syncthreads();
        float* Yp = Y + ((size_t)b * C_ + o0 + row) * HW_ + s0 + h * 64 + cq;
#pragma unroll
        for (int j = 0; j < 4; j++) {
            float4 v = *(const float4*)&stg[row * 68 + cq + 4 * j];
            *(float4*)(Yp + 4 * j) = v;
            s  += v.x + v.y + v.z + v.w;
            ss += v.x * v.x + v.y * v.y + v.z * v.z + v.w * v.w;
        }
    }
    atomicAdd(&sg[row >> 3][0], s);
    atomicAdd(&sg[row >> 3][1], ss);
    __syncthreads();
    if (tid < 32)
        atomicAdd(&g_psum[which][b][(o0 >> 3) + (tid >> 1)][tid & 1], sg[tid >> 1][tid & 1]);
}

// ---------------------------------------------------------------------------
// Kernel 3: per-patch attention (unchanged from best passing version)
// ---------------------------------------------------------------------------
#define ATTN_SMEM ((256 * AST + 2 * 32 * AST + 64 * AST) * 4)

__global__ __launch_bounds__(256, 2) void attn_kernel(
    const float* __restrict__ xlow,
    const float* __restrict__ gq, const float* __restrict__ bq,
    const float* __restrict__ gk, const float* __restrict__ bk,
    float* __restrict__ out)
{
    extern __shared__ __align__(16) float sm[];
    float* ks   = sm;
    float* bufQ = sm + 256 * AST;
    float* A    = sm + (256 + 64) * AST;

    const int n  = blockIdx.x;
    const int b  = n >> 8;
    const int ph = (n >> 4) & 15;
    const int pw = n & 15;
    const int tid = threadIdx.x;
    const size_t pbase = (size_t)b * C_ * HW_ + (size_t)(ph * 8) * W_ + pw * 8;

    const int cl = tid >> 3, il = tid & 7;
    const size_t lbase = pbase + (size_t)il * W_;

#pragma unroll
    for (int pass = 0; pass < 8; pass++) {
        const int c = pass * 32 + cl;
        const float2 st = g_stats[1][b][c >> 3];
        const float ak = st.y * __ldg(gk + c), ck = __ldg(bk + c) - st.x * ak;
        const float* src = g_Yk + lbase + (size_t)c * HW_;
        float4 v0 = *(const float4*)src;
        float4 v1 = *(const float4*)(src + 4);
        *(float4*)&ks[c * AST + il * 8]     = make_float4(v0.x*ak+ck, v0.y*ak+ck, v0.z*ak+ck, v0.w*ak+ck);
        *(float4*)&ks[c * AST + il * 8 + 4] = make_float4(v1.x*ak+ck, v1.y*ak+ck, v1.z*ak+ck, v1.w*ak+ck);
    }

    float4 q0, q1; float aq, cq;
    {
        const int c = cl;
        const float2 st = g_stats[0][b][c >> 3];
        aq = st.y * __ldg(gq + c); cq = __ldg(bq + c) - st.x * aq;
        const float* src = g_Yq + lbase + (size_t)c * HW_;
        q0 = *(const float4*)src; q1 = *(const float4*)(src + 4);
    }
    *(float4*)&bufQ[cl * AST + il * 8]     = make_float4(q0.x*aq+cq, q0.y*aq+cq, q0.z*aq+cq, q0.w*aq+cq);
    *(float4*)&bufQ[cl * AST + il * 8 + 4] = make_float4(q1.x*aq+cq, q1.y*aq+cq, q1.z*aq+cq, q1.w*aq+cq);
    __syncthreads();

    const int tx = tid & 15, ty = tid >> 4;
    u64 sacc[4][2];
#pragma unroll
    for (int m = 0; m < 4; m++) { sacc[m][0] = 0ull; sacc[m][1] = 0ull; }

    for (int ch = 0; ch < 8; ch++) {
        const int buf = ch & 1;
        if (ch < 7) {
            const int c = (ch + 1) * 32 + cl;
            const float2 st = g_stats[0][b][c >> 3];
            aq = st.y * __ldg(gq + c); cq = __ldg(bq + c) - st.x * aq;
            const float* src = g_Yq + lbase + (size_t)c * HW_;
            q0 = *(const float4*)src; q1 = *(const float4*)(src + 4);
        }
        const float* bq_ = bufQ + buf * 32 * AST + 4 * ty;
        const float* ks_ = ks + (ch * 32) * AST + 4 * tx;
#pragma unroll 4
        for (int cc = 0; cc < 32; cc++) {
            float4 qv = *(const float4*)(bq_ + cc * AST);
            ulonglong2 kv = *(const ulonglong2*)(ks_ + cc * AST);
            u64 qp0 = bcast2(qv.x), qp1 = bcast2(qv.y), qp2 = bcast2(qv.z), qp3 = bcast2(qv.w);
            FMA2(sacc[0][0], qp0, kv.x); FMA2(sacc[0][1], qp0, kv.y);
            FMA2(sacc[1][0], qp1, kv.x); FMA2(sacc[1][1], qp1, kv.y);
            FMA2(sacc[2][0], qp2, kv.x); FMA2(sacc[2][1], qp2, kv.y);
            FMA2(sacc[3][0], qp3, kv.x); FMA2(sacc[3][1], qp3, kv.y);
        }
        if (ch < 7) {
            __syncthreads();
            const int nb = buf ^ 1;
            *(float4*)&bufQ[nb * 32 * AST + cl * AST + il * 8]     = make_float4(q0.x*aq+cq, q0.y*aq+cq, q0.z*aq+cq, q0.w*aq+cq);
            *(float4*)&bufQ[nb * 32 * AST + cl * AST + il * 8 + 4] = make_float4(q1.x*aq+cq, q1.y*aq+cq, q1.z*aq+cq, q1.w*aq+cq);
            __syncthreads();
        }
    }
#pragma unroll
    for (int m = 0; m < 4; m++)
        *(ulonglong2*)&A[(4 * ty + m) * AST + 4 * tx] = make_ulonglong2(sacc[m][0], sacc[m][1]);
    __syncthreads();

    {
        float* row = A + (tid >> 2) * AST + (tid & 3) * 16;
        float mx = -1e30f;
#pragma unroll
        for (int j = 0; j < 16; j++) mx = fmaxf(mx, row[j] * 0.0625f);
        mx = fmaxf(mx, __shfl_xor_sync(0xffffffffu, mx, 1));
        mx = fmaxf(mx, __shfl_xor_sync(0xffffffffu, mx, 2));
        float s = 0.f;
#pragma unroll
        for (int j = 0; j < 16; j++) { float e = __expf(row[j] * 0.0625f - mx); row[j] = e; s += e; }
        s += __shfl_xor_sync(0xffffffffu, s, 1);
        s += __shfl_xor_sync(0xffffffffu, s, 2);
        const float inv = 1.0f / s;
#pragma unroll
        for (int j = 0; j < 16; j++) row[j] *= inv;
    }
    __syncthreads();

    const int pg = tid & 7, cg = tid >> 3;
#pragma unroll 1
    for (int h = 0; h < 2; h++) {
        u64 oacc[8][4];
#pragma unroll
        for (int jp = 0; jp < 8; jp++)
#pragma unroll
            for (int jc = 0; jc < 4; jc++) oacc[jp][jc] = 0ull;

        const float* kb = ks + (h * 128 + cg) * AST;
#pragma unroll 4
        for (int ppb = 0; ppb < 16; ppb++) {
            ulonglong2 ap[8];
#pragma unroll
            for (int jp = 0; jp < 8; jp++)
                ap[jp] = *(const ulonglong2*)&A[(pg + 8 * jp) * AST + 4 * ppb];
#pragma unroll
            for (int jc = 0; jc < 4; jc++) {
                ulonglong2 kp = *(const ulonglong2*)(kb + jc * 32 * AST + 4 * ppb);
#pragma unroll
                for (int jp = 0; jp < 8; jp++) {
                    FMA2(oacc[jp][jc], ap[jp].x, kp.x);
                    FMA2(oacc[jp][jc], ap[jp].y, kp.y);
                }
            }
        }
#pragma unroll
        for (int jc = 0; jc < 4; jc++) {
            const int c = h * 128 + cg + 32 * jc;
            const size_t cb = pbase + (size_t)c * HW_ + pg;
#pragma unroll
            for (int jp = 0; jp < 8; jp++) {
                float2 v = unpack2(oacc[jp][jc]);
                const size_t off = cb + (size_t)jp * W_;
                out[off] = v.x + v.y + __ldg(xlow + off);
            }
        }
    }
}

// ---------------------------------------------------------------------------
// Launch
// ---------------------------------------------------------------------------
extern "C" void kernel_launch(void* const* d_in, const int* in_sizes, int n_in,
                              void* d_out, int out_size)
{
    const float* x_low  = (const float*)d_in[0];
    const float* x_high = (const float*)d_in[1];
    const float* Wq     = (const float*)d_in[2];
    const float* gq     = (const float*)d_in[3];
    const float* bq     = (const float*)d_in[4];
    const float* Wk     = (const float*)d_in[5];
    const float* gk     = (const float*)d_in[6];
    const float* bk     = (const float*)d_in[7];
    float* out = (float*)d_out;

    cudaFuncSetAttribute(conv_tc_kernel, cudaFuncAttributeMaxDynamicSharedMemorySize, CONV_SMEM);
    cudaFuncSetAttribute(attn_kernel, cudaFuncAttributeMaxDynamicSharedMemorySize, ATTN_SMEM);

    init_kernel<<<1, 1024>>>();
    wprep_kernel<<<512, 256>>>(Wq, Wk);

    // both convs in one launch; x fastest so o-twins share the X tile in L2
    conv_tc_kernel<<<dim3(2, 128, 16), 512, CONV_SMEM>>>(x_low, x_high);
    gn_finalize<<<1, 512>>>();
    attn_kernel<<<2048, 256, ATTN_SMEM>>>(x_low, gq, bq, gk, bk, out);
}

// round 16
// speedup vs baseline: 1.9947x; 1.0570x over previous
#include <cuda_runtime.h>
#include <cuda_bf16.h>
#include <cstdint>
#include <mma.h>

using namespace nvcuda;

#define B_      8
#define C_      256
#define H_      128
#define W_      128
#define HW_     (H_ * W_)
#define GROUPS_ 32
#define CPG_    8
#define EPS_    1e-5f

typedef unsigned long long u64;
typedef __nv_bfloat16 bf16;

// ---------------------------------------------------------------------------
// Scratch
// ---------------------------------------------------------------------------
__device__ float  g_Yq[(size_t)B_ * C_ * HW_];
__device__ float  g_Yk[(size_t)B_ * C_ * HW_];
__device__ __align__(16) bf16 g_Wbh[2][C_ * C_];   // bf16(v)
__device__ __align__(16) bf16 g_Wbl[2][C_ * C_];   // bf16(v - hi)
__device__ float  g_psum[2][B_][GROUPS_][2];
__device__ float2 g_stats[2][B_][GROUPS_];

// ---------------------------------------------------------------------------
// small kernels
// ---------------------------------------------------------------------------
__global__ void init_kernel() { ((float*)g_psum)[threadIdx.x] = 0.f; }

__global__ __launch_bounds__(256) void wprep_kernel(
    const float* __restrict__ Wq, const float* __restrict__ Wk)
{
    const int i = blockIdx.x * 256 + threadIdx.x;      // 512 blocks -> 131072
    const int t = i >> 16, j = i & 65535;
    const float v  = (t ? Wk : Wq)[j];
    const bf16 hi = __float2bfloat16_rn(v);
    const bf16 lo = __float2bfloat16_rn(v - __bfloat162float(hi));
    g_Wbh[t][j] = hi;
    g_Wbl[t][j] = lo;
}

__global__ void gn_finalize() {
    const int t = threadIdx.x;
    const int te = t >> 8, b = (t >> 5) & 7, g = t & 31;
    const float inv = 1.0f / (float)(CPG_ * HW_);
    float mu  = g_psum[te][b][g][0] * inv;
    float var = g_psum[te][b][g][1] * inv - mu * mu;
    g_stats[te][b][g] = make_float2(mu, rsqrtf(fmaxf(var, 0.f) + EPS_));
}

// ---------------------------------------------------------------------------
// Conv: WMMA bf16 m16n16k16, 3-term split, double-buffered (proven R15)
// ---------------------------------------------------------------------------
#define OFF_AL  5120
#define OFF_BH  10240
#define OFF_BL  14592
#define STG_EL  18944
#define CONV_SMEM (STG_EL * 2 * 2)

using FragA  = wmma::fragment<wmma::matrix_a, 16, 16, 16, bf16, wmma::row_major>;
using FragB  = wmma::fragment<wmma::matrix_b, 16, 16, 16, bf16, wmma::row_major>;
using FragAc = wmma::fragment<wmma::matrix_a, 16, 16, 16, bf16, wmma::col_major>;
using FragBc = wmma::fragment<wmma::matrix_b, 16, 16, 16, bf16, wmma::col_major>;
using FragC  = wmma::fragment<wmma::accumulator, 16, 16, 16, float>;

__global__ __launch_bounds__(512, 1) void conv_tc_kernel(
    const float* __restrict__ X0, const float* __restrict__ X1)
{
    extern __shared__ __align__(16) bf16 smh[];
    __shared__ float sg[16][2];

    const int tid = threadIdx.x;
    const int wid = tid >> 5;
    const int warp_m = wid & 3;
    const int warp_n = wid >> 2;
    const int o0 = blockIdx.x * 128;
    const int s0 = blockIdx.y * 128;
    const int which = blockIdx.z >> 3;
    const int b  = blockIdx.z & 7;

    const float*  X  = which ? X1 : X0;
    float* __restrict__ Y = which ? g_Yk : g_Yq;
    const bf16* Wbh = g_Wbh[which];
    const bf16* Wbl = g_Wbl[which];

    FragC acc[2][2];
#pragma unroll
    for (int tm = 0; tm < 2; tm++)
#pragma unroll
        for (int tn = 0; tn < 2; tn++) wmma::fill_fragment(acc[tm][tn], 0.f);

    const int wrow = tid >> 2, wseg = (tid & 3) * 8;
    const int xrow = tid >> 4, xseg = (tid & 15) * 8;

    uint4 whv, wlv;
    float xv[8];
    {
        whv = *(const uint4*)&Wbh[(size_t)(o0 + wrow) * C_ + wseg];
        wlv = *(const uint4*)&Wbl[(size_t)(o0 + wrow) * C_ + wseg];
        const float* xp = X + ((size_t)b * C_ + xrow) * HW_ + s0 + xseg;
        *(float4*)&xv[0] = *(const float4*)xp;
        *(float4*)&xv[4] = *(const float4*)(xp + 4);
    }
    {
        *(uint4*)&smh[wrow * 40 + wseg]          = whv;
        *(uint4*)&smh[OFF_AL + wrow * 40 + wseg] = wlv;
        __align__(16) bf16 hh[8], ll[8];
#pragma unroll
        for (int j = 0; j < 8; j++) {
            hh[j] = __float2bfloat16_rn(xv[j]);
            ll[j] = __float2bfloat16_rn(xv[j] - __bfloat162float(hh[j]));
        }
        *(uint4*)&smh[OFF_BH + xrow * 136 + xseg] = *(uint4*)hh;
        *(uint4*)&smh[OFF_BL + xrow * 136 + xseg] = *(uint4*)ll;
    }
    if (tid < 32) ((float*)sg)[tid] = 0.f;
    __syncthreads();

    for (int ch = 0; ch < 8; ch++) {
        const bf16* cb = smh + (ch & 1) * STG_EL;

        if (ch < 7) {
            const int c0 = (ch + 1) * 32;
            whv = *(const uint4*)&Wbh[(size_t)(o0 + wrow) * C_ + c0 + wseg];
            wlv = *(const uint4*)&Wbl[(size_t)(o0 + wrow) * C_ + c0 + wseg];
            const float* xp = X + ((size_t)b * C_ + c0 + xrow) * HW_ + s0 + xseg;
            *(float4*)&xv[0] = *(const float4*)xp;
            *(float4*)&xv[4] = *(const float4*)(xp + 4);
        }

#pragma unroll
        for (int t = 0; t < 2; t++) {
            FragA ah[2], al[2];
#pragma unroll
            for (int tm = 0; tm < 2; tm++) {
                const int ao = (warp_m * 32 + tm * 16) * 40 + t * 16;
                wmma::load_matrix_sync(ah[tm], cb + ao, 40);
                wmma::load_matrix_sync(al[tm], cb + OFF_AL + ao, 40);
            }
#pragma unroll
            for (int tn = 0; tn < 2; tn++) {
                FragB bh, bl;
                const int bo = (t * 16) * 136 + warp_n * 32 + tn * 16;
                wmma::load_matrix_sync(bh, cb + OFF_BH + bo, 136);
                wmma::load_matrix_sync(bl, cb + OFF_BL + bo, 136);
#pragma unroll
                for (int tm = 0; tm < 2; tm++) {
                    wmma::mma_sync(acc[tm][tn], ah[tm], bh, acc[tm][tn]);
                    wmma::mma_sync(acc[tm][tn], ah[tm], bl, acc[tm][tn]);
                    wmma::mma_sync(acc[tm][tn], al[tm], bh, acc[tm][tn]);
                }
            }
        }

        if (ch < 7) {
            bf16* nb = smh + ((ch + 1) & 1) * STG_EL;
            *(uint4*)&nb[wrow * 40 + wseg]          = whv;
            *(uint4*)&nb[OFF_AL + wrow * 40 + wseg] = wlv;
            __align__(16) bf16 hh[8], ll[8];
#pragma unroll
            for (int j = 0; j < 8; j++) {
                hh[j] = __float2bfloat16_rn(xv[j]);
                ll[j] = __float2bfloat16_rn(xv[j] - __bfloat162float(hh[j]));
            }
            *(uint4*)&nb[OFF_BH + xrow * 136 + xseg] = *(uint4*)hh;
            *(uint4*)&nb[OFF_BL + xrow * 136 + xseg] = *(uint4*)ll;
        }
        __syncthreads();
    }

    // epilogue in TWO 64-column halves (proven R13)
    float* stg = (float*)smh;
    float s = 0.f, ss = 0.f;
    const int row = tid >> 2, cq = (tid & 3) * 16;
#pragma unroll
    for (int h = 0; h < 2; h++) {
        __syncthreads();
        if ((warp_n >> 1) == h) {
#pragma unroll
            for (int tm = 0; tm < 2; tm++)
#pragma unroll
                for (int tn = 0; tn < 2; tn++)
                    wmma::store_matrix_sync(
                        &stg[(warp_m * 32 + tm * 16) * 68 + (warp_n & 1) * 32 + tn * 16],
                        acc[tm][tn], 68, wmma::mem_row_major);
        }
        __syncthreads();
        float* Yp = Y + ((size_t)b * C_ + o0 + row) * HW_ + s0 + h * 64 + cq;
#pragma unroll
        for (int j = 0; j < 4; j++) {
            float4 v = *(const float4*)&stg[row * 68 + cq + 4 * j];
            *(float4*)(Yp + 4 * j) = v;
            s  += v.x + v.y + v.z + v.w;
            ss += v.x * v.x + v.y * v.y + v.z * v.z + v.w * v.w;
        }
    }
    atomicAdd(&sg[row >> 3][0], s);
    atomicAdd(&sg[row >> 3][1], ss);
    __syncthreads();
    if (tid < 32)
        atomicAdd(&g_psum[which][b][(o0 >> 3) + (tid >> 1)][tid & 1], sg[tid >> 1][tid & 1]);
}

// ---------------------------------------------------------------------------
// Attention via WMMA bf16 3-term split. One CTA (512 thr) per patch.
// All operands in natural [c][p] layout; col_major fragments do the
// "transposes" (S: q as matrix_a/col_major; O: k as matrix_b/col_major).
// smem (bytes):
//   q_hi [256][72]bf16 @0       q_lo @36864      (region reused as Ostg f32 [256][68])
//   k_hi [256][72]bf16 @73728   k_lo @110592
//   S    [64][68]f32   @147456
//   A_hi [64][72]bf16  @164864  A_lo @174080     total 183296 B
// ---------------------------------------------------------------------------
#define AQ_HI   0
#define AQ_LO   18432       // bf16 elements
#define AK_HI   36864
#define AK_LO   55296
#define AS_F    (147456 / 4)   // float index
#define AA_HI   82432       // bf16 el index (164864/2)
#define AA_LO   87040       // (174080/2)
#define ATTN_SMEM 183296

__global__ __launch_bounds__(512, 1) void attn_kernel(
    const float* __restrict__ xlow,
    const float* __restrict__ gq, const float* __restrict__ bq,
    const float* __restrict__ gk, const float* __restrict__ bk,
    float* __restrict__ out)
{
    extern __shared__ __align__(16) char smc[];
    bf16*  smb = (bf16*)smc;
    float* smf = (float*)smc;
    float* Sf  = smf + AS_F;          // [64][68] f32
    float* Ostg = smf;                // [256][68] f32 (overlays q region)

    const int n  = blockIdx.x;
    const int b  = n >> 8;
    const int ph = (n >> 4) & 15;
    const int pw = n & 15;
    const int tid = threadIdx.x;
    const int wid = tid >> 5;
    const size_t pbase = (size_t)b * C_ * HW_ + (size_t)(ph * 8) * W_ + pw * 8;

    // ---- phase 1: load + normalize + bf16-split q,k into [c][72] ----
    {
        const int cl = tid >> 3, il = tid & 7;     // 64 c x 8 rows
        const size_t lbase = pbase + (size_t)il * W_;
#pragma unroll
        for (int pass = 0; pass < 4; pass++) {
            const int c = pass * 64 + cl;
            const float2 stq = g_stats[0][b][c >> 3];
            const float aq = stq.y * __ldg(gq + c), cq0 = __ldg(bq + c) - stq.x * aq;
            const float2 stk = g_stats[1][b][c >> 3];
            const float ak = stk.y * __ldg(gk + c), ck0 = __ldg(bk + c) - stk.x * ak;
            const float* srcq = g_Yq + lbase + (size_t)c * HW_;
            const float* srck = g_Yk + lbase + (size_t)c * HW_;
            float vq[8], vk[8];
            *(float4*)&vq[0] = *(const float4*)srcq;
            *(float4*)&vq[4] = *(const float4*)(srcq + 4);
            *(float4*)&vk[0] = *(const float4*)srck;
            *(float4*)&vk[4] = *(const float4*)(srck + 4);
            __align__(16) bf16 qh[8], ql[8], kh[8], kl[8];
#pragma unroll
            for (int j = 0; j < 8; j++) {
                const float q = vq[j] * aq + cq0;
                const float k = vk[j] * ak + ck0;
                qh[j] = __float2bfloat16_rn(q);
                ql[j] = __float2bfloat16_rn(q - __bfloat162float(qh[j]));
                kh[j] = __float2bfloat16_rn(k);
                kl[j] = __float2bfloat16_rn(k - __bfloat162float(kh[j]));
            }
            *(uint4*)&smb[AQ_HI + c * 72 + il * 8] = *(uint4*)qh;
            *(uint4*)&smb[AQ_LO + c * 72 + il * 8] = *(uint4*)ql;
            *(uint4*)&smb[AK_HI + c * 72 + il * 8] = *(uint4*)kh;
            *(uint4*)&smb[AK_LO + c * 72 + il * 8] = *(uint4*)kl;
        }
    }
    __syncthreads();

    // ---- phase 2: S = q^T k  (16 warps: 4x4 16x16 tiles) ----
    {
        const int sp  = (wid >> 2) * 16;   // p tile
        const int spp = (wid & 3) * 16;    // p' tile
        FragC accS;
        wmma::fill_fragment(accS, 0.f);
#pragma unroll
        for (int cs = 0; cs < 256; cs += 16) {
            FragAc qh_f, ql_f;
            wmma::load_matrix_sync(qh_f, smb + AQ_HI + cs * 72 + sp, 72);
            wmma::load_matrix_sync(ql_f, smb + AQ_LO + cs * 72 + sp, 72);
            FragB kh_f, kl_f;
            wmma::load_matrix_sync(kh_f, smb + AK_HI + cs * 72 + spp, 72);
            wmma::load_matrix_sync(kl_f, smb + AK_LO + cs * 72 + spp, 72);
            wmma::mma_sync(accS, qh_f, kh_f, accS);
            wmma::mma_sync(accS, qh_f, kl_f, accS);
            wmma::mma_sync(accS, ql_f, kh_f, accS);
        }
        wmma::store_matrix_sync(Sf + sp * 68 + spp, accS, 68, wmma::mem_row_major);
    }
    __syncthreads();

    // ---- phase 3: row softmax on Sf (proven code; warps 0-7) ----
    if (tid < 256) {
        float* row = Sf + (tid >> 2) * 68 + (tid & 3) * 16;
        float mx = -1e30f;
#pragma unroll
        for (int j = 0; j < 16; j++) mx = fmaxf(mx, row[j] * 0.0625f);
        mx = fmaxf(mx, __shfl_xor_sync(0xffffffffu, mx, 1));
        mx = fmaxf(mx, __shfl_xor_sync(0xffffffffu, mx, 2));
        float s = 0.f;
#pragma unroll
        for (int j = 0; j < 16; j++) { float e = __expf(row[j] * 0.0625f - mx); row[j] = e; s += e; }
        s += __shfl_xor_sync(0xffffffffu, s, 1);
        s += __shfl_xor_sync(0xffffffffu, s, 2);
        const float inv = 1.0f / s;
#pragma unroll
        for (int j = 0; j < 16; j++) row[j] *= inv;
    }
    __syncthreads();

    // ---- phase 4: convert A -> bf16 hi/lo [p][72] ----
    {
        const int p = tid >> 3, s8 = (tid & 7) * 8;
        __align__(16) bf16 hh[8], ll[8];
        const float* src = Sf + p * 68 + s8;
#pragma unroll
        for (int j = 0; j < 8; j++) {
            const float v = src[j];
            hh[j] = __float2bfloat16_rn(v);
            ll[j] = __float2bfloat16_rn(v - __bfloat162float(hh[j]));
        }
        *(uint4*)&smb[AA_HI + p * 72 + s8] = *(uint4*)hh;
        *(uint4*)&smb[AA_LO + p * 72 + s8] = *(uint4*)ll;
    }
    __syncthreads();

    // ---- phase 5: O = A k^T  (16 warps: 4 p-tiles x 4 c-quarters) ----
    {
        const int op  = (wid & 3) * 16;    // p tile
        const int oc0 = (wid >> 2) * 64;   // c quarter (4 tiles)
        FragC accO[4];
#pragma unroll
        for (int t = 0; t < 4; t++) wmma::fill_fragment(accO[t], 0.f);
#pragma unroll
        for (int ps = 0; ps < 64; ps += 16) {
            FragA ah_f, al_f;
            wmma::load_matrix_sync(ah_f, smb + AA_HI + op * 72 + ps, 72);
            wmma::load_matrix_sync(al_f, smb + AA_LO + op * 72 + ps, 72);
#pragma unroll
            for (int t = 0; t < 4; t++) {
                FragBc kh_f, kl_f;
                wmma::load_matrix_sync(kh_f, smb + AK_HI + (oc0 + t * 16) * 72 + ps, 72);
                wmma::load_matrix_sync(kl_f, smb + AK_LO + (oc0 + t * 16) * 72 + ps, 72);
                wmma::mma_sync(accO[t], ah_f, kh_f, accO[t]);
                wmma::mma_sync(accO[t], ah_f, kl_f, accO[t]);
                wmma::mma_sync(accO[t], al_f, kh_f, accO[t]);
            }
        }
        // store O transposed into Ostg[c][p] (col_major store), overlaying q region
#pragma unroll
        for (int t = 0; t < 4; t++)
            wmma::store_matrix_sync(Ostg + (oc0 + t * 16) * 68 + op, accO[t], 68,
                                    wmma::mem_col_major);
    }
    __syncthreads();

    // ---- phase 6: coalesced writeback with residual ----
    for (int u = tid; u < C_ * 16; u += 512) {
        const int c = u >> 4, i = (u >> 1) & 7, jh = u & 1;
        const size_t off = pbase + (size_t)c * HW_ + (size_t)i * W_ + jh * 4;
        float4 o4 = *(const float4*)&Ostg[c * 68 + i * 8 + jh * 4];
        float4 xl = *(const float4*)(xlow + off);
        *(float4*)(out + off) = make_float4(o4.x + xl.x, o4.y + xl.y, o4.z + xl.z, o4.w + xl.w);
    }
}

// ---------------------------------------------------------------------------
// Launch
// ---------------------------------------------------------------------------
extern "C" void kernel_launch(void* const* d_in, const int* in_sizes, int n_in,
                              void* d_out, int out_size)
{
    const float* x_low  = (const float*)d_in[0];
    const float* x_high = (const float*)d_in[1];
    const float* Wq     = (const float*)d_in[2];
    const float* gq     = (const float*)d_in[3];
    const float* bq     = (const float*)d_in[4];
    const float* Wk     = (const float*)d_in[5];
    const float* gk     = (const float*)d_in[6];
    const float* bk     = (const float*)d_in[7];
    float* out = (float*)d_out;

    cudaFuncSetAttribute(conv_tc_kernel, cudaFuncAttributeMaxDynamicSharedMemorySize, CONV_SMEM);
    cudaFuncSetAttribute(attn_kernel, cudaFuncAttributeMaxDynamicSharedMemorySize, ATTN_SMEM);

    init_kernel<<<1, 1024>>>();
    wprep_kernel<<<512, 256>>>(Wq, Wk);

    conv_tc_kernel<<<dim3(2, 128, 16), 512, CONV_SMEM>>>(x_low, x_high);
    gn_finalize<<<1, 512>>>();
    attn_kernel<<<2048, 512, ATTN_SMEM>>>(x_low, gq, bq, gk, bk, out);
}